// round 14
// baseline (speedup 1.0000x reference)
#include <cuda_runtime.h>
#include <cstdint>

#define B_      8
#define V_      50000
#define C_      256
#define PC_     64
#define K_      9
#define KIN1_   (K_ * PC_)          // 576
#define M_TOTAL (B_ * V_)           // 400000
#define TILE_M  128

// ---- SMEM layout (32-bit words), 2 CTAs/SM (identical to r13) ----
#define P_OFF      0
#define P_ST       68                   // 68 % 32 == 4 -> conflict-free
#define OFFS_OFF   8704
#define AS1A_OFF   9856
#define AS1B_OFF   14464
#define BS1A_OFF   19072
#define BS1B_OFF   21376
#define BS2A_OFF   8704
#define BS2B_OFF   13312
#define AXA_OFF    17920
#define AXB_OFF    22528
#define S_ST       36                   // 36 % 32 == 4
#define SMEM_WORDS 27136                // 108544 bytes -> 2 CTAs/SM
#define NCH1       18                   // phase-1 k-chunks of 32

__device__ __forceinline__ uint32_t smem_u32(const void* p) {
    uint32_t a;
    asm("{ .reg .u64 t; cvta.to.shared.u64 t, %1; cvt.u32.u64 %0, t; }" : "=r"(a) : "l"(p));
    return a;
}

// 16B global->shared async copy, L1-bypass (.cg). sm_80+ feature, legal on sm_103.
#define CP16(dst, src) \
    asm volatile("cp.async.cg.shared.global [%0], [%1], 16;" :: "r"(dst), "l"(src) : "memory")
#define CP_COMMIT() asm volatile("cp.async.commit_group;" ::: "memory")
#define CP_WAIT0()  asm volatile("cp.async.wait_group 0;" ::: "memory")

// fp32 -> tf32 round-to-nearest (single HW instr).
__device__ __forceinline__ unsigned cvt_tf(float f) {
    unsigned o;
    asm("cvt.rna.tf32.f32 %0, %1;" : "=r"(o) : "f"(f));
    return o;
}
// LDS word + tf32 convert at fragment-load time (idempotent on already-tf32 data).
__device__ __forceinline__ unsigned ldcvt(const unsigned* p) {
    return cvt_tf(__uint_as_float(*p));
}

__device__ __forceinline__ void mma8(float* c, const unsigned* a, unsigned u0, unsigned u1) {
    asm volatile(
        "mma.sync.aligned.m16n8k8.row.col.f32.tf32.tf32.f32 "
        "{%0,%1,%2,%3}, {%4,%5,%6,%7}, {%8,%9}, {%0,%1,%2,%3};"
        : "+f"(c[0]), "+f"(c[1]), "+f"(c[2]), "+f"(c[3])
        : "r"(a[0]), "r"(a[1]), "r"(a[2]), "r"(a[3]), "r"(u0), "r"(u1));
}

__global__ void __launch_bounds__(256, 2)
fused_spiral(const float* x,
             const int* idx,            // int32 (JAX x64 disabled)
             const float* W1,
             const float* b1,
             const float* W2,
             const float* b2,
             float* out)
{
    extern __shared__ unsigned sm[];
    unsigned* Pp   = sm + P_OFF;
    int*      offs = (int*)(sm + OFFS_OFF);
    const uint32_t sb = smem_u32(sm);

    const int tid = threadIdx.x;
    const int m0  = blockIdx.x * TILE_M;
    const int warp = tid >> 5, lane = tid & 31;
    const int wm = warp & 3;                 // m group: wm*32 (both phases)
    const int wn = warp >> 2;                // n group (ph1: wn*32, ph2: wn*64)
    const int lg = lane >> 2, lq = lane & 3;

    // ---- Gather row offsets; defensive clamp ----
    for (int i = tid; i < TILE_M * K_; i += 256) {
        int r = i / K_;
        int k = i - r * K_;
        int m = m0 + r;
        int b = m / V_;
        int v = m - b * V_;
        int id = idx[v * K_ + k];
        id = id < 0 ? 0 : (id >= V_ ? V_ - 1 : id);
        offs[i] = (b * V_ + id) * C_;
    }
    __syncthreads();   // offs visible before any gather cp.async

    // ================= Phase 1: gather + GEMM1 (128x64, K=576), k-chunks of 32 =================
    float acc1[2][4][4];
    #pragma unroll
    for (int i = 0; i < 2; i++)
        #pragma unroll
        for (int j = 0; j < 4; j++)
            #pragma unroll
            for (int l = 0; l < 4; l++) acc1[i][j][l] = 0.f;

    const int arow = tid >> 1, ah = tid & 1;     // A loader: row, 16-float half of 32
    const int brow = tid >> 2, bq = tid & 3;     // B loader: out-row, 8-float quarter

    const uint32_t dA1[2] = { sb + (AS1A_OFF + arow * S_ST + ah * 16) * 4,
                              sb + (AS1B_OFF + arow * S_ST + ah * 16) * 4 };
    const uint32_t dB1[2] = { sb + (BS1A_OFF + brow * S_ST + bq * 8) * 4,
                              sb + (BS1B_OFF + brow * S_ST + bq * 8) * 4 };

    // prologue: issue chunk 0
    {
        const float* sA = x + offs[arow * K_] + ah * 16;
        #pragma unroll
        for (int j = 0; j < 4; j++) CP16(dA1[0] + j * 16, sA + j * 4);
        const float* sB = W1 + brow * KIN1_ + bq * 8;
        CP16(dB1[0], sB);
        CP16(dB1[0] + 16, sB + 4);
        CP_COMMIT();
    }

    for (int kc = 0; kc < NCH1; kc++) {
        CP_WAIT0();            // my copies for chunk kc complete
        __syncthreads();       // everyone's copies complete; prev buffer free
        if (kc + 1 < NCH1) {   // issue chunk kc+1 (overlaps mma below)
            int g = (kc + 1) >> 1, h = (kc + 1) & 1;
            int bf = (kc + 1) & 1;
            const float* sA = x + offs[arow * K_ + g] + h * 32 + ah * 16;
            #pragma unroll
            for (int j = 0; j < 4; j++) CP16(dA1[bf] + j * 16, sA + j * 4);
            const float* sB = W1 + brow * KIN1_ + (kc + 1) * 32 + bq * 8;
            CP16(dB1[bf], sB);
            CP16(dB1[bf] + 16, sB + 4);
            CP_COMMIT();
        }

        const unsigned* As = sm + ((kc & 1) ? AS1B_OFF : AS1A_OFF);
        const unsigned* Bs = sm + ((kc & 1) ? BS1B_OFF : BS1A_OFF);
        #pragma unroll
        for (int kk = 0; kk < 32; kk += 8) {
            unsigned a[2][4];
            #pragma unroll
            for (int ms = 0; ms < 2; ms++) {
                const unsigned* p = As + (wm * 32 + ms * 16 + lg) * S_ST + kk + lq;
                a[ms][0] = ldcvt(p);
                a[ms][1] = ldcvt(p + 8 * S_ST);
                a[ms][2] = ldcvt(p + 4);
                a[ms][3] = ldcvt(p + 8 * S_ST + 4);
            }
            #pragma unroll
            for (int ns = 0; ns < 4; ns++) {
                const unsigned* p = Bs + (wn * 32 + ns * 8 + lg) * S_ST + kk + lq;
                unsigned u0 = ldcvt(p), u1 = ldcvt(p + 4);
                mma8(acc1[0][ns], a[0], u0, u1);
                mma8(acc1[1][ns], a[1], u0, u1);
            }
        }
    }
    __syncthreads();   // all ph1 mma reads done before overlay region is rewritten

    // ---- P epilogue: + b1, tf32 (rna), into P region ----
    #pragma unroll
    for (int ms = 0; ms < 2; ms++) {
        #pragma unroll
        for (int ns = 0; ns < 4; ns++) {
            int row = wm * 32 + ms * 16 + lg;
            int col = wn * 32 + ns * 8 + lq * 2;
            float bv0 = b1[col], bv1 = b1[col + 1];
            *(uint2*)(Pp + row * P_ST + col) =
                make_uint2(cvt_tf(acc1[ms][ns][0] + bv0), cvt_tf(acc1[ms][ns][1] + bv1));
            *(uint2*)(Pp + (row + 8) * P_ST + col) =
                make_uint2(cvt_tf(acc1[ms][ns][2] + bv0), cvt_tf(acc1[ms][ns][3] + bv1));
        }
    }

    // ================= Phase 2: out = [P|xu](128x256) @ W2^T + b2 =================
    // 4m x 2n warps, warp tile 32x64, two nc passes. A: kc 0-1 from P; kc 2-7 xu ring.
    const int wrow = tid >> 1, wh = tid & 1;   // W2 loader: out-row, 16-float half

    const uint32_t dW2[2] = { sb + (BS2A_OFF + wrow * S_ST + wh * 16) * 4,
                              sb + (BS2B_OFF + wrow * S_ST + wh * 16) * 4 };
    const uint32_t dX2[2] = { sb + (AXA_OFF + arow * S_ST + ah * 16) * 4,
                              sb + (AXB_OFF + arow * S_ST + ah * 16) * 4 };

    {   // prologue: W2 slab s=0 (safe: after post-ph1 sync)
        const float* sB = W2 + (size_t)wrow * C_ + wh * 16;
        #pragma unroll
        for (int j = 0; j < 4; j++) CP16(dW2[0] + j * 16, sB + j * 4);
        CP_COMMIT();
    }

    int s = 0;
    #pragma unroll
    for (int nc = 0; nc < 2; nc++) {
        float acc2[2][8][4];
        #pragma unroll
        for (int i = 0; i < 2; i++)
            #pragma unroll
            for (int j = 0; j < 8; j++)
                #pragma unroll
                for (int l = 0; l < 4; l++) acc2[i][j][l] = 0.f;

        for (int kc = 0; kc < 8; kc++, s++) {
            CP_WAIT0();            // slab s data complete (mine)
            __syncthreads();       // all threads' copies complete; old buffers free
            if (s + 1 < 16) {      // issue slab s+1 (overlaps mma below)
                int nn = (s + 1) >> 3, kk2 = (s + 1) & 7;
                int bf = (s + 1) & 1;
                const float* sB = W2 + (size_t)(nn * 128 + wrow) * C_ + kk2 * 32 + wh * 16;
                #pragma unroll
                for (int j = 0; j < 4; j++) CP16(dW2[bf] + j * 16, sB + j * 4);
                if (kk2 >= 2) {
                    const float* sX =
                        x + (size_t)(m0 + arow) * C_ + PC_ + (kk2 - 2) * 32 + ah * 16;
                    #pragma unroll
                    for (int j = 0; j < 4; j++) CP16(dX2[bf] + j * 16, sX + j * 4);
                }
                CP_COMMIT();
            }

            const unsigned* Bs = sm + ((s & 1) ? BS2B_OFF : BS2A_OFF);
            const unsigned* Abase = (kc < 2) ? (Pp + kc * 32)
                                             : (sm + ((s & 1) ? AXB_OFF : AXA_OFF));
            const int ast = (kc < 2) ? P_ST : S_ST;

            #pragma unroll
            for (int kk = 0; kk < 32; kk += 8) {
                unsigned a[2][4];
                #pragma unroll
                for (int ms = 0; ms < 2; ms++) {
                    const unsigned* p = Abase + (wm * 32 + ms * 16 + lg) * ast + kk + lq;
                    a[ms][0] = ldcvt(p);
                    a[ms][1] = ldcvt(p + 8 * ast);
                    a[ms][2] = ldcvt(p + 4);
                    a[ms][3] = ldcvt(p + 8 * ast + 4);
                }
                #pragma unroll
                for (int ns = 0; ns < 8; ns++) {
                    const unsigned* p = Bs + (wn * 64 + ns * 8 + lg) * S_ST + kk + lq;
                    unsigned u0 = ldcvt(p), u1 = ldcvt(p + 4);
                    mma8(acc2[0][ns], a[0], u0, u1);
                    mma8(acc2[1][ns], a[1], u0, u1);
                }
            }
        }

        // epilogue: + b2 (global, L2-hot), store out cols [nc*128, nc*128+128)
        #pragma unroll
        for (int ms = 0; ms < 2; ms++) {
            #pragma unroll
            for (int ns = 0; ns < 8; ns++) {
                int row = m0 + wm * 32 + ms * 16 + lg;
                int col = nc * 128 + wn * 64 + ns * 8 + lq * 2;
                float bv0 = b2[col], bv1 = b2[col + 1];
                *(float2*)(out + (size_t)row * C_ + col) =
                    make_float2(acc2[ms][ns][0] + bv0, acc2[ms][ns][1] + bv1);
                *(float2*)(out + (size_t)(row + 8) * C_ + col) =
                    make_float2(acc2[ms][ns][2] + bv0, acc2[ms][ns][3] + bv1);
            }
        }
    }
}

extern "C" void kernel_launch(void* const* d_in, const int* in_sizes, int n_in,
                              void* d_out, int out_size) {
    const float* x   = (const float*)d_in[0];
    const int*   idx = (const int*)d_in[1];
    const float* W1  = (const float*)d_in[2];
    const float* b1  = (const float*)d_in[3];
    const float* W2  = (const float*)d_in[4];
    const float* b2  = (const float*)d_in[5];
    float*       out = (float*)d_out;

    const int smem = SMEM_WORDS * 4;   // 108544 bytes -> 2 CTAs/SM
    cudaFuncSetAttribute(fused_spiral, cudaFuncAttributeMaxDynamicSharedMemorySize, smem);
    fused_spiral<<<M_TOTAL / TILE_M, 256, smem>>>(x, idx, W1, b1, W2, b2, out);
}

// round 15
// speedup vs baseline: 1.0455x; 1.0455x over previous
#include <cuda_runtime.h>
#include <cstdint>

#define B_      8
#define V_      50000
#define C_      256
#define PC_     64
#define K_      9
#define KIN1_   (K_ * PC_)          // 576
#define M_TOTAL (B_ * V_)           // 400000
#define TILE_M  128

// ---- SMEM layout (32-bit words), 2 CTAs/SM (identical to r13/r14) ----
#define P_OFF      0
#define P_ST       68                   // 68 % 32 == 4 -> conflict-free
#define OFFS_OFF   8704
#define AS1A_OFF   9856
#define AS1B_OFF   14464
#define BS1A_OFF   19072
#define BS1B_OFF   21376
#define BS2A_OFF   8704
#define BS2B_OFF   13312
#define AXA_OFF    17920
#define AXB_OFF    22528
#define S_ST       36                   // 36 % 32 == 4
#define SMEM_WORDS 27136                // 108544 bytes -> 2 CTAs/SM
#define NCH1       18                   // phase-1 k-chunks of 32

__device__ __forceinline__ uint32_t smem_u32(const void* p) {
    uint32_t a;
    asm("{ .reg .u64 t; cvta.to.shared.u64 t, %1; cvt.u32.u64 %0, t; }" : "=r"(a) : "l"(p));
    return a;
}

// 16B global->shared async copy, L1-bypass (.cg).
#define CP16(dst, src) \
    asm volatile("cp.async.cg.shared.global [%0], [%1], 16;" :: "r"(dst), "l"(src) : "memory")
#define CP_COMMIT() asm volatile("cp.async.commit_group;" ::: "memory")
#define CP_WAIT0()  asm volatile("cp.async.wait_group 0;" ::: "memory")

// fp32 -> tf32 round-to-nearest (single HW instr).
__device__ __forceinline__ unsigned cvt_tf(float f) {
    unsigned o;
    asm("cvt.rna.tf32.f32 %0, %1;" : "=r"(o) : "f"(f));
    return o;
}
__device__ __forceinline__ uint4 cvt_tf4(float4 v) {
    return make_uint4(cvt_tf(v.x), cvt_tf(v.y), cvt_tf(v.z), cvt_tf(v.w));
}
// LDS word + tf32 convert (for raw-fp32 slabs: gather-A, xu).
__device__ __forceinline__ unsigned ldcvt(const unsigned* p) {
    return cvt_tf(__uint_as_float(*p));
}

__device__ __forceinline__ void mma8(float* c, const unsigned* a, unsigned u0, unsigned u1) {
    asm volatile(
        "mma.sync.aligned.m16n8k8.row.col.f32.tf32.tf32.f32 "
        "{%0,%1,%2,%3}, {%4,%5,%6,%7}, {%8,%9}, {%0,%1,%2,%3};"
        : "+f"(c[0]), "+f"(c[1]), "+f"(c[2]), "+f"(c[3])
        : "r"(a[0]), "r"(a[1]), "r"(a[2]), "r"(a[3]), "r"(u0), "r"(u1));
}

__global__ void __launch_bounds__(256, 2)
fused_spiral(const float* x,
             const int* idx,            // int32 (JAX x64 disabled)
             const float* W1,
             const float* b1,
             const float* W2,
             const float* b2,
             float* out)
{
    extern __shared__ unsigned sm[];
    unsigned* Pp   = sm + P_OFF;
    int*      offs = (int*)(sm + OFFS_OFF);
    const uint32_t sb = smem_u32(sm);

    const int tid = threadIdx.x;
    const int m0  = blockIdx.x * TILE_M;
    const int warp = tid >> 5, lane = tid & 31;
    const int wm = warp & 3;                 // m group: wm*32 (both phases)
    const int wn = warp >> 2;                // n group (ph1: wn*32, ph2: wn*64)
    const int lg = lane >> 2, lq = lane & 3;

    // ---- Gather row offsets; defensive clamp ----
    for (int i = tid; i < TILE_M * K_; i += 256) {
        int r = i / K_;
        int k = i - r * K_;
        int m = m0 + r;
        int b = m / V_;
        int v = m - b * V_;
        int id = idx[v * K_ + k];
        id = id < 0 ? 0 : (id >= V_ ? V_ - 1 : id);
        offs[i] = (b * V_ + id) * C_;
    }
    __syncthreads();   // offs visible before any gather cp.async

    // ================= Phase 1: gather + GEMM1 (128x64, K=576), k-chunks of 32 =================
    float acc1[2][4][4];
    #pragma unroll
    for (int i = 0; i < 2; i++)
        #pragma unroll
        for (int j = 0; j < 4; j++)
            #pragma unroll
            for (int l = 0; l < 4; l++) acc1[i][j][l] = 0.f;

    const int arow = tid >> 1, ah = tid & 1;     // A loader: row, 16-float half of 32
    const int brow = tid >> 2, bq = tid & 3;     // B loader: out-row, 8-float quarter

    const uint32_t dA1[2] = { sb + (AS1A_OFF + arow * S_ST + ah * 16) * 4,
                              sb + (AS1B_OFF + arow * S_ST + ah * 16) * 4 };

    float4 pb[2];   // W1 prefetch regs (r13 mechanism: cvt at STS, pure B fragments)
    {   // prologue: cp.async A chunk 0; LDG W1 chunk 0
        const float* sA = x + offs[arow * K_] + ah * 16;
        #pragma unroll
        for (int j = 0; j < 4; j++) CP16(dA1[0] + j * 16, sA + j * 4);
        CP_COMMIT();
        const float4* sB = (const float4*)(W1 + brow * KIN1_ + bq * 8);
        pb[0] = sB[0]; pb[1] = sB[1];
    }

    for (int kc = 0; kc < NCH1; kc++) {
        {   // STS W1 slab (tf32 at store); safe pre-sync (buffer last read mma kc-2)
            unsigned* dB = sm + ((kc & 1) ? BS1B_OFF : BS1A_OFF) + brow * S_ST + bq * 8;
            *(uint4*)(dB)     = cvt_tf4(pb[0]);
            *(uint4*)(dB + 4) = cvt_tf4(pb[1]);
        }
        CP_WAIT0();            // my A copies for chunk kc complete
        __syncthreads();       // all copies/STS visible; prev A buffer free
        if (kc + 1 < NCH1) {   // overlap with mma below
            int g = (kc + 1) >> 1, h = (kc + 1) & 1;
            const float* sA = x + offs[arow * K_ + g] + h * 32 + ah * 16;
            #pragma unroll
            for (int j = 0; j < 4; j++) CP16(dA1[(kc + 1) & 1] + j * 16, sA + j * 4);
            CP_COMMIT();
            const float4* sB = (const float4*)(W1 + brow * KIN1_ + (kc + 1) * 32 + bq * 8);
            pb[0] = sB[0]; pb[1] = sB[1];
        }

        const unsigned* As = sm + ((kc & 1) ? AS1B_OFF : AS1A_OFF);
        const unsigned* Bs = sm + ((kc & 1) ? BS1B_OFF : BS1A_OFF);
        #pragma unroll
        for (int kk = 0; kk < 32; kk += 8) {
            unsigned a[2][4];
            #pragma unroll
            for (int ms = 0; ms < 2; ms++) {
                const unsigned* p = As + (wm * 32 + ms * 16 + lg) * S_ST + kk + lq;
                a[ms][0] = ldcvt(p);
                a[ms][1] = ldcvt(p + 8 * S_ST);
                a[ms][2] = ldcvt(p + 4);
                a[ms][3] = ldcvt(p + 8 * S_ST + 4);
            }
            #pragma unroll
            for (int ns = 0; ns < 4; ns++) {
                const unsigned* p = Bs + (wn * 32 + ns * 8 + lg) * S_ST + kk + lq;
                unsigned u0 = p[0], u1 = p[4];   // already tf32: pure LDS
                mma8(acc1[0][ns], a[0], u0, u1);
                mma8(acc1[1][ns], a[1], u0, u1);
            }
        }
    }
    __syncthreads();   // all ph1 mma reads done before overlay region is rewritten

    // ---- P epilogue: + b1, tf32 (rna), into P region ----
    #pragma unroll
    for (int ms = 0; ms < 2; ms++) {
        #pragma unroll
        for (int ns = 0; ns < 4; ns++) {
            int row = wm * 32 + ms * 16 + lg;
            int col = wn * 32 + ns * 8 + lq * 2;
            float bv0 = b1[col], bv1 = b1[col + 1];
            *(uint2*)(Pp + row * P_ST + col) =
                make_uint2(cvt_tf(acc1[ms][ns][0] + bv0), cvt_tf(acc1[ms][ns][1] + bv1));
            *(uint2*)(Pp + (row + 8) * P_ST + col) =
                make_uint2(cvt_tf(acc1[ms][ns][2] + bv0), cvt_tf(acc1[ms][ns][3] + bv1));
        }
    }

    // ================= Phase 2: out = [P|xu](128x256) @ W2^T + b2 =================
    // 4m x 2n warps, warp tile 32x64, two nc passes. A: kc 0-1 from P (pure);
    // kc 2-7 xu via cp.async (fragment cvt). W2 via reg-prefetch + STS-cvt (pure).
    const int wrow = tid >> 1, wh = tid & 1;   // W2 loader: out-row, 16-float half
    const uint32_t dX2[2] = { sb + (AXA_OFF + arow * S_ST + ah * 16) * 4,
                              sb + (AXB_OFF + arow * S_ST + ah * 16) * 4 };

    float4 pw[4];
    {   // prologue: LDG W2 slab s=0
        const float4* sB = (const float4*)(W2 + (size_t)wrow * C_ + wh * 16);
        #pragma unroll
        for (int j = 0; j < 4; j++) pw[j] = sB[j];
    }

    int s = 0;
    #pragma unroll
    for (int nc = 0; nc < 2; nc++) {
        float acc2[2][8][4];
        #pragma unroll
        for (int i = 0; i < 2; i++)
            #pragma unroll
            for (int j = 0; j < 8; j++)
                #pragma unroll
                for (int l = 0; l < 4; l++) acc2[i][j][4 - 4 + l] = 0.f;

        for (int kc = 0; kc < 8; kc++, s++) {
            {   // STS W2 slab (tf32 at store); safe pre-sync
                unsigned* dB = sm + ((s & 1) ? BS2B_OFF : BS2A_OFF) + wrow * S_ST + wh * 16;
                #pragma unroll
                for (int j = 0; j < 4; j++) *(uint4*)(dB + j * 4) = cvt_tf4(pw[j]);
            }
            CP_WAIT0();            // xu slab s (if any) complete
            __syncthreads();       // all visible; old buffers free
            if (s + 1 < 16) {      // overlap with mma below
                int nn = (s + 1) >> 3, kk2 = (s + 1) & 7;
                const float4* sB = (const float4*)(
                    W2 + (size_t)(nn * 128 + wrow) * C_ + kk2 * 32 + wh * 16);
                #pragma unroll
                for (int j = 0; j < 4; j++) pw[j] = sB[j];
                if (kk2 >= 2) {
                    const float* sX =
                        x + (size_t)(m0 + arow) * C_ + PC_ + (kk2 - 2) * 32 + ah * 16;
                    #pragma unroll
                    for (int j = 0; j < 4; j++) CP16(dX2[(s + 1) & 1] + j * 16, sX + j * 4);
                    CP_COMMIT();
                }
            }

            const unsigned* Bs = sm + ((s & 1) ? BS2B_OFF : BS2A_OFF);

            if (kc < 2) {   // A from P: already tf32, pure LDS
                const unsigned* Abase = Pp + kc * 32;
                #pragma unroll
                for (int kk = 0; kk < 32; kk += 8) {
                    unsigned a[2][4];
                    #pragma unroll
                    for (int ms = 0; ms < 2; ms++) {
                        const unsigned* p = Abase + (wm * 32 + ms * 16 + lg) * P_ST + kk + lq;
                        a[ms][0] = p[0];
                        a[ms][1] = p[8 * P_ST];
                        a[ms][2] = p[4];
                        a[ms][3] = p[8 * P_ST + 4];
                    }
                    #pragma unroll
                    for (int ns = 0; ns < 8; ns++) {
                        const unsigned* p = Bs + (wn * 64 + ns * 8 + lg) * S_ST + kk + lq;
                        unsigned u0 = p[0], u1 = p[4];
                        mma8(acc2[0][ns], a[0], u0, u1);
                        mma8(acc2[1][ns], a[1], u0, u1);
                    }
                }
            } else {        // A from xu ring: raw fp32, fragment cvt
                const unsigned* Abase = sm + ((s & 1) ? AXB_OFF : AXA_OFF);
                #pragma unroll
                for (int kk = 0; kk < 32; kk += 8) {
                    unsigned a[2][4];
                    #pragma unroll
                    for (int ms = 0; ms < 2; ms++) {
                        const unsigned* p = Abase + (wm * 32 + ms * 16 + lg) * S_ST + kk + lq;
                        a[ms][0] = ldcvt(p);
                        a[ms][1] = ldcvt(p + 8 * S_ST);
                        a[ms][2] = ldcvt(p + 4);
                        a[ms][3] = ldcvt(p + 8 * S_ST + 4);
                    }
                    #pragma unroll
                    for (int ns = 0; ns < 8; ns++) {
                        const unsigned* p = Bs + (wn * 64 + ns * 8 + lg) * S_ST + kk + lq;
                        unsigned u0 = p[0], u1 = p[4];
                        mma8(acc2[0][ns], a[0], u0, u1);
                        mma8(acc2[1][ns], a[1], u0, u1);
                    }
                }
            }
        }

        // epilogue: + b2 (global, L2-hot), store out cols [nc*128, nc*128+128)
        #pragma unroll
        for (int ms = 0; ms < 2; ms++) {
            #pragma unroll
            for (int ns = 0; ns < 8; ns++) {
                int row = m0 + wm * 32 + ms * 16 + lg;
                int col = nc * 128 + wn * 64 + ns * 8 + lq * 2;
                float bv0 = b2[col], bv1 = b2[col + 1];
                *(float2*)(out + (size_t)row * C_ + col) =
                    make_float2(acc2[ms][ns][0] + bv0, acc2[ms][ns][1] + bv1);
                *(float2*)(out + (size_t)(row + 8) * C_ + col) =
                    make_float2(acc2[ms][ns][2] + bv0, acc2[ms][ns][3] + bv1);
            }
        }
    }
}

extern "C" void kernel_launch(void* const* d_in, const int* in_sizes, int n_in,
                              void* d_out, int out_size) {
    const float* x   = (const float*)d_in[0];
    const int*   idx = (const int*)d_in[1];
    const float* W1  = (const float*)d_in[2];
    const float* b1  = (const float*)d_in[3];
    const float* W2  = (const float*)d_in[4];
    const float* b2  = (const float*)d_in[5];
    float*       out = (float*)d_out;

    const int smem = SMEM_WORDS * 4;   // 108544 bytes -> 2 CTAs/SM
    cudaFuncSetAttribute(fused_spiral, cudaFuncAttributeMaxDynamicSharedMemorySize, smem);
    fused_spiral<<<M_TOTAL / TILE_M, 256, smem>>>(x, idx, W1, b1, W2, b2, out);
}

// round 16
// speedup vs baseline: 1.0820x; 1.0350x over previous
#include <cuda_runtime.h>
#include <cstdint>

#define B_      8
#define V_      50000
#define C_      256
#define PC_     64
#define K_      9
#define KIN1_   (K_ * PC_)          // 576
#define M_TOTAL (B_ * V_)           // 400000
#define TILE_M  128

// ---- SMEM layout (32-bit words), 3 CTAs/SM (75776 B/CTA) ----
// ph1: A1A@0, A1B@4608 (128x36 each) | offs@9216 | BS1A@10368, BS1B@12672 (64x36)
// ph2: P@0 (128x68, overlays dead A-ring) | BS2A@9216, BS2B@11520 (64x36)
//      AXA@13824, AXB@16384 (128x20)
#define P_OFF      0
#define P_ST       68                   // 68 % 32 == 4 -> conflict-free
#define A1A_OFF    0
#define A1B_OFF    4608
#define OFFS_OFF   9216
#define BS1A_OFF   10368
#define BS1B_OFF   12672
#define BS2A_OFF   9216
#define BS2B_OFF   11520
#define AXA_OFF    13824
#define AXB_OFF    16384
#define S_ST       36                   // 36 % 32 == 4
#define AX_ST      20                   // lg*20 mod 32 distinct -> conflict-free
#define SMEM_WORDS 18944                // 75776 bytes -> 3 CTAs/SM
#define NCH1       18                   // phase-1 k-chunks of 32

__device__ __forceinline__ uint32_t smem_u32(const void* p) {
    uint32_t a;
    asm("{ .reg .u64 t; cvta.to.shared.u64 t, %1; cvt.u32.u64 %0, t; }" : "=r"(a) : "l"(p));
    return a;
}

// 16B global->shared async copy, L1-bypass (.cg).
#define CP16(dst, src) \
    asm volatile("cp.async.cg.shared.global [%0], [%1], 16;" :: "r"(dst), "l"(src) : "memory")
#define CP_COMMIT() asm volatile("cp.async.commit_group;" ::: "memory")
#define CP_WAIT0()  asm volatile("cp.async.wait_group 0;" ::: "memory")

// fp32 -> tf32 round-to-nearest (single HW instr).
__device__ __forceinline__ unsigned cvt_tf(float f) {
    unsigned o;
    asm("cvt.rna.tf32.f32 %0, %1;" : "=r"(o) : "f"(f));
    return o;
}
__device__ __forceinline__ uint4 cvt_tf4(float4 v) {
    return make_uint4(cvt_tf(v.x), cvt_tf(v.y), cvt_tf(v.z), cvt_tf(v.w));
}
// LDS word + tf32 convert (for raw-fp32 slabs: gather-A, xu).
__device__ __forceinline__ unsigned ldcvt(const unsigned* p) {
    return cvt_tf(__uint_as_float(*p));
}

__device__ __forceinline__ void mma8(float* c, const unsigned* a, unsigned u0, unsigned u1) {
    asm volatile(
        "mma.sync.aligned.m16n8k8.row.col.f32.tf32.tf32.f32 "
        "{%0,%1,%2,%3}, {%4,%5,%6,%7}, {%8,%9}, {%0,%1,%2,%3};"
        : "+f"(c[0]), "+f"(c[1]), "+f"(c[2]), "+f"(c[3])
        : "r"(a[0]), "r"(a[1]), "r"(a[2]), "r"(a[3]), "r"(u0), "r"(u1));
}

__global__ void __launch_bounds__(256, 3)
fused_spiral(const float* x,
             const int* idx,            // int32 (JAX x64 disabled)
             const float* W1,
             const float* b1,
             const float* W2,
             const float* b2,
             float* out)
{
    extern __shared__ unsigned sm[];
    unsigned* Pp   = sm + P_OFF;
    int*      offs = (int*)(sm + OFFS_OFF);
    const uint32_t sb = smem_u32(sm);

    const int tid = threadIdx.x;
    const int m0  = blockIdx.x * TILE_M;
    const int warp = tid >> 5, lane = tid & 31;
    const int wm = warp & 3;                 // m group: wm*32 (both phases)
    const int wn = warp >> 2;                // n group (ph1: wn*32 of 64; ph2: wn*32 of 64)
    const int lg = lane >> 2, lq = lane & 3;

    // ---- Gather row offsets; defensive clamp ----
    for (int i = tid; i < TILE_M * K_; i += 256) {
        int r = i / K_;
        int k = i - r * K_;
        int m = m0 + r;
        int b = m / V_;
        int v = m - b * V_;
        int id = idx[v * K_ + k];
        id = id < 0 ? 0 : (id >= V_ ? V_ - 1 : id);
        offs[i] = (b * V_ + id) * C_;
    }
    __syncthreads();   // offs visible before any gather cp.async

    // ================= Phase 1: gather + GEMM1 (128x64, K=576), k-chunks of 32 =================
    float acc1[2][4][4];
    #pragma unroll
    for (int i = 0; i < 2; i++)
        #pragma unroll
        for (int j = 0; j < 4; j++)
            #pragma unroll
            for (int l = 0; l < 4; l++) acc1[i][j][l] = 0.f;

    const int arow = tid >> 1, ah = tid & 1;     // A loader: row, 16-float half of 32
    const int brow = tid >> 2, bq = tid & 3;     // B loader: out-row, 8-float quarter

    const uint32_t dA1[2] = { sb + (A1A_OFF + arow * S_ST + ah * 16) * 4,
                              sb + (A1B_OFF + arow * S_ST + ah * 16) * 4 };

    float4 pb[2];   // W1 prefetch regs (cvt at STS, pure B fragments)
    {   // prologue: cp.async A chunk 0; LDG W1 chunk 0
        const float* sA = x + offs[arow * K_] + ah * 16;
        #pragma unroll
        for (int j = 0; j < 4; j++) CP16(dA1[0] + j * 16, sA + j * 4);
        CP_COMMIT();
        const float4* sB = (const float4*)(W1 + brow * KIN1_ + bq * 8);
        pb[0] = sB[0]; pb[1] = sB[1];
    }

    for (int kc = 0; kc < NCH1; kc++) {
        {   // STS W1 slab (tf32 at store); safe pre-sync (buffer last read mma kc-2)
            unsigned* dB = sm + ((kc & 1) ? BS1B_OFF : BS1A_OFF) + brow * S_ST + bq * 8;
            *(uint4*)(dB)     = cvt_tf4(pb[0]);
            *(uint4*)(dB + 4) = cvt_tf4(pb[1]);
        }
        CP_WAIT0();            // my A copies for chunk kc complete
        __syncthreads();       // all copies/STS visible; prev A buffer free
        if (kc + 1 < NCH1) {   // overlap with mma below
            int g = (kc + 1) >> 1, h = (kc + 1) & 1;
            const float* sA = x + offs[arow * K_ + g] + h * 32 + ah * 16;
            #pragma unroll
            for (int j = 0; j < 4; j++) CP16(dA1[(kc + 1) & 1] + j * 16, sA + j * 4);
            CP_COMMIT();
            const float4* sB = (const float4*)(W1 + brow * KIN1_ + (kc + 1) * 32 + bq * 8);
            pb[0] = sB[0]; pb[1] = sB[1];
        }

        const unsigned* As = sm + ((kc & 1) ? A1B_OFF : A1A_OFF);
        const unsigned* Bs = sm + ((kc & 1) ? BS1B_OFF : BS1A_OFF);
        #pragma unroll
        for (int kk = 0; kk < 32; kk += 8) {
            unsigned a[2][4];
            #pragma unroll
            for (int ms = 0; ms < 2; ms++) {
                const unsigned* p = As + (wm * 32 + ms * 16 + lg) * S_ST + kk + lq;
                a[ms][0] = ldcvt(p);
                a[ms][1] = ldcvt(p + 8 * S_ST);
                a[ms][2] = ldcvt(p + 4);
                a[ms][3] = ldcvt(p + 8 * S_ST + 4);
            }
            #pragma unroll
            for (int ns = 0; ns < 4; ns++) {
                const unsigned* p = Bs + (wn * 32 + ns * 8 + lg) * S_ST + kk + lq;
                unsigned u0 = p[0], u1 = p[4];   // already tf32: pure LDS
                mma8(acc1[0][ns], a[0], u0, u1);
                mma8(acc1[1][ns], a[1], u0, u1);
            }
        }
    }
    __syncthreads();   // all ph1 mma reads done; A-ring region becomes P

    // ---- P epilogue: + b1, tf32 (rna), into P region (overlays dead A-ring) ----
    #pragma unroll
    for (int ms = 0; ms < 2; ms++) {
        #pragma unroll
        for (int ns = 0; ns < 4; ns++) {
            int row = wm * 32 + ms * 16 + lg;
            int col = wn * 32 + ns * 8 + lq * 2;
            float bv0 = b1[col], bv1 = b1[col + 1];
            *(uint2*)(Pp + row * P_ST + col) =
                make_uint2(cvt_tf(acc1[ms][ns][0] + bv0), cvt_tf(acc1[ms][ns][1] + bv1));
            *(uint2*)(Pp + (row + 8) * P_ST + col) =
                make_uint2(cvt_tf(acc1[ms][ns][2] + bv0), cvt_tf(acc1[ms][ns][3] + bv1));
        }
    }

    // ================= Phase 2: out = [P|xu](128x256) @ W2^T + b2 =================
    // 4 nc-passes of N=64; warps 4m x 2n, warp tile 32x32; k-chunks of 16.
    // A: kc 0-3 from P (pure LDS); kc 4-15 xu via cp.async ring (fragment cvt).
    // W2: k32 slabs (reg-prefetch + STS-cvt, pure B fragments), 2 chunks per slab.
    const int wrow2 = tid >> 2, wq2 = tid & 3;   // W2: row(0..63), 8-float quarter
    const uint32_t dX2[2] = { sb + (AXA_OFF + arow * AX_ST + ah * 8) * 4,
                              sb + (AXB_OFF + arow * AX_ST + ah * 8) * 4 };

    float4 pw[2];
    {   // prologue: LDG W2 slab 0 (rows 0..63, k 0..31)
        const float4* sB = (const float4*)(W2 + (size_t)wrow2 * C_ + wq2 * 8);
        pw[0] = sB[0]; pw[1] = sB[1];
    }

    int s = 0;                               // global k16-chunk counter (0..63)
    for (int nc = 0; nc < 4; nc++) {
        float acc2[2][4][4];
        #pragma unroll
        for (int i = 0; i < 2; i++)
            #pragma unroll
            for (int j = 0; j < 4; j++)
                #pragma unroll
                for (int l = 0; l < 4; l++) acc2[i][j][l] = 0.f;

        for (int kc = 0; kc < 16; kc++, s++) {
            const int sj = s >> 1;           // global W2 k32-slab index (0..31)
            if ((kc & 1) == 0) {             // STS W2 slab sj (pre-sync; buffer free)
                unsigned* dB = sm + ((sj & 1) ? BS2B_OFF : BS2A_OFF)
                             + wrow2 * S_ST + wq2 * 8;
                *(uint4*)(dB)     = cvt_tf4(pw[0]);
                *(uint4*)(dB + 4) = cvt_tf4(pw[1]);
            }
            CP_WAIT0();                      // xu slab for this chunk (if any) complete
            __syncthreads();                 // all visible; old buffers free
            if (s + 1 < 64) {                // prefetch for chunk s+1 (overlaps mma)
                if (kc & 1) {                // LDG W2 slab sj+1 (STS'd next chunk)
                    const int nsl = sj + 1;
                    const float4* sB = (const float4*)(
                        W2 + (size_t)((nsl >> 3) * 64 + wrow2) * C_
                           + (nsl & 7) * 32 + wq2 * 8);
                    pw[0] = sB[0]; pw[1] = sB[1];
                }
                const int kn = (s + 1) & 15;
                if (kn >= 4) {               // cp.async xu for chunk s+1
                    const float* sX = x + (size_t)(m0 + arow) * C_ + PC_
                                    + (kn - 4) * 16 + ah * 8;
                    CP16(dX2[(s + 1) & 1], sX);
                    CP16(dX2[(s + 1) & 1] + 16, sX + 4);
                }
                CP_COMMIT();
            }

            const unsigned* Bs = sm + ((sj & 1) ? BS2B_OFF : BS2A_OFF);
            const int kb = (kc & 1) * 16;    // k-offset inside the k32 W2 slab

            if (kc < 4) {                    // A from P: tf32, pure LDS
                const unsigned* Abase = Pp + kc * 16;
                #pragma unroll
                for (int kk = 0; kk < 16; kk += 8) {
                    unsigned a[2][4];
                    #pragma unroll
                    for (int ms = 0; ms < 2; ms++) {
                        const unsigned* p = Abase + (wm * 32 + ms * 16 + lg) * P_ST + kk + lq;
                        a[ms][0] = p[0];
                        a[ms][1] = p[8 * P_ST];
                        a[ms][2] = p[4];
                        a[ms][3] = p[8 * P_ST + 4];
                    }
                    #pragma unroll
                    for (int ns = 0; ns < 4; ns++) {
                        const unsigned* p = Bs + (wn * 32 + ns * 8 + lg) * S_ST + kb + kk + lq;
                        unsigned u0 = p[0], u1 = p[4];
                        mma8(acc2[0][ns], a[0], u0, u1);
                        mma8(acc2[1][ns], a[1], u0, u1);
                    }
                }
            } else {                         // A from xu ring: raw fp32, fragment cvt
                const unsigned* Abase = sm + ((s & 1) ? AXB_OFF : AXA_OFF);
                #pragma unroll
                for (int kk = 0; kk < 16; kk += 8) {
                    unsigned a[2][4];
                    #pragma unroll
                    for (int ms = 0; ms < 2; ms++) {
                        const unsigned* p = Abase + (wm * 32 + ms * 16 + lg) * AX_ST + kk + lq;
                        a[ms][0] = ldcvt(p);
                        a[ms][1] = ldcvt(p + 8 * AX_ST);
                        a[ms][2] = ldcvt(p + 4);
                        a[ms][3] = ldcvt(p + 8 * AX_ST + 4);
                    }
                    #pragma unroll
                    for (int ns = 0; ns < 4; ns++) {
                        const unsigned* p = Bs + (wn * 32 + ns * 8 + lg) * S_ST + kb + kk + lq;
                        unsigned u0 = p[0], u1 = p[4];
                        mma8(acc2[0][ns], a[0], u0, u1);
                        mma8(acc2[1][ns], a[1], u0, u1);
                    }
                }
            }
        }

        // epilogue: + b2 (global, L2-hot), store out cols [nc*64, nc*64+64)
        #pragma unroll
        for (int ms = 0; ms < 2; ms++) {
            #pragma unroll
            for (int ns = 0; ns < 4; ns++) {
                int row = m0 + wm * 32 + ms * 16 + lg;
                int col = nc * 64 + wn * 32 + ns * 8 + lq * 2;
                float bv0 = b2[col], bv1 = b2[col + 1];
                *(float2*)(out + (size_t)row * C_ + col) =
                    make_float2(acc2[ms][ns][0] + bv0, acc2[ms][ns][1] + bv1);
                *(float2*)(out + (size_t)(row + 8) * C_ + col) =
                    make_float2(acc2[ms][ns][2] + bv0, acc2[ms][ns][3] + bv1);
            }
        }
    }
}

extern "C" void kernel_launch(void* const* d_in, const int* in_sizes, int n_in,
                              void* d_out, int out_size) {
    const float* x   = (const float*)d_in[0];
    const int*   idx = (const int*)d_in[1];
    const float* W1  = (const float*)d_in[2];
    const float* b1  = (const float*)d_in[3];
    const float* W2  = (const float*)d_in[4];
    const float* b2  = (const float*)d_in[5];
    float*       out = (float*)d_out;

    const int smem = SMEM_WORDS * 4;   // 75776 bytes -> 3 CTAs/SM
    cudaFuncSetAttribute(fused_spiral, cudaFuncAttributeMaxDynamicSharedMemorySize, smem);
    fused_spiral<<<M_TOTAL / TILE_M, 256, smem>>>(x, idx, W1, b1, W2, b2, out);
}